// round 11
// baseline (speedup 1.0000x reference)
#include <cuda_runtime.h>
#include <cuda_bf16.h>
#include <math.h>
#include <stdint.h>

// ---------------------------------------------------------------------------
// Problem constants
// ---------------------------------------------------------------------------
#define BATCH   4
#define SEQL    2048
#define DMODEL  256
#define DINNER  512
#define NSTATE  16
#define NTOK    (BATCH * SEQL)          // 8192
#define RMS_EPS 1.1920929e-07f

#define NCH     64                       // scan chunks
#define CT      (SEQL / NCH)             // 32 steps per chunk
#define NDBC    576                      // padded N for fused delta/B/C gemm (544 real)

// ---------------------------------------------------------------------------
// Scratch (static device globals; no allocation allowed)
// ---------------------------------------------------------------------------
__device__ __nv_bfloat16 g_xnb  [(size_t)NTOK * DMODEL];      // rmsnorm (bf16)
__device__ __nv_bfloat16 g_xzb  [(size_t)NTOK * 2 * DINNER];  // x_branch|z bf16
__device__ __nv_bfloat16 g_xcb  [(size_t)NTOK * DINNER];      // conv+silu bf16
__device__ __nv_bfloat16 g_deltab[(size_t)NTOK * DINNER];     // softplus(delta) bf16
__device__ float         g_BC   [(size_t)NTOK * 32];          // B(16) | C(16)
__device__ __nv_bfloat16 g_Winb [(size_t)(2 * DINNER) * DMODEL];
__device__ __nv_bfloat16 g_Wdbcb[(size_t)NDBC * DINNER];
__device__ __nv_bfloat16 g_Woutb[(size_t)DMODEL * DINNER];
__device__ __nv_bfloat16 g_yb   [(size_t)NTOK * DINNER];
__device__ float g_sdl[(size_t)BATCH * NCH * DINNER];          // per-chunk sum(delta)
__device__ float g_S  [(size_t)BATCH * NCH * NSTATE * DINNER];
__device__ float g_H  [(size_t)BATCH * NCH * NSTATE * DINNER];

// ---------------------------------------------------------------------------
// Helpers
// ---------------------------------------------------------------------------
__device__ __forceinline__ float ex2f(float x) {       // single MUFU.EX2
    float r;
    asm("ex2.approx.ftz.f32 %0, %1;" : "=f"(r) : "f"(x));
    return r;
}
__device__ __forceinline__ float silu_f(float v) { return v / (1.0f + __expf(-v)); }
__device__ __forceinline__ float softplus_f(float v) {
    return (v > 20.0f) ? v : __logf(1.0f + __expf(v));
}
__device__ __forceinline__ void mma_bf16(float (&d)[4], const uint32_t (&a)[4],
                                         const uint32_t (&b)[2]) {
    asm volatile(
        "mma.sync.aligned.m16n8k16.row.col.f32.bf16.bf16.f32 "
        "{%0,%1,%2,%3},{%4,%5,%6,%7},{%8,%9},{%0,%1,%2,%3};"
        : "+f"(d[0]), "+f"(d[1]), "+f"(d[2]), "+f"(d[3])
        : "r"(a[0]), "r"(a[1]), "r"(a[2]), "r"(a[3]), "r"(b[0]), "r"(b[1]));
}
#define LDSM_X4(r0, r1, r2, r3, addr)                                        \
    asm volatile("ldmatrix.sync.aligned.m8n8.x4.shared.b16 {%0,%1,%2,%3}, [%4];" \
                 : "=r"(r0), "=r"(r1), "=r"(r2), "=r"(r3) : "r"(addr))
#define CP_ASYNC16(dst, src) \
    asm volatile("cp.async.cg.shared.global [%0], [%1], 16;" :: "r"(dst), "l"(src))
#define CP_COMMIT() asm volatile("cp.async.commit_group;")

// ---------------------------------------------------------------------------
// Weight prep: bf16 conversions (+ norm_w folded into in_proj weights)
// ---------------------------------------------------------------------------
#define WIN_E  (2 * DINNER * DMODEL)    // 262144
#define WDBC_E (NDBC * DINNER)          // 294912
#define WOUT_E (DMODEL * DINNER)        // 131072
__global__ void prep_w_kernel(const float* __restrict__ win,
                              const float* __restrict__ normw,
                              const float* __restrict__ wd,
                              const float* __restrict__ wb,
                              const float* __restrict__ wc,
                              const float* __restrict__ wout) {
    int idx = blockIdx.x * blockDim.x + threadIdx.x;
    if (idx < WIN_E) {
        int k = idx & (DMODEL - 1);
        g_Winb[idx] = __float2bfloat16(win[idx] * normw[k]);
    }
    int j = idx - WIN_E;
    if (j >= 0 && j < WDBC_E) {
        int r = j / DINNER;
        int k = j - r * DINNER;
        float v;
        if      (r < 512) v = wd[(size_t)r * DINNER + k];
        else if (r < 528) v = wb[(size_t)(r - 512) * DINNER + k];
        else if (r < 544) v = wc[(size_t)(r - 528) * DINNER + k];
        else              v = 0.0f;
        g_Wdbcb[j] = __float2bfloat16(v);
    }
    int q = idx - WIN_E - WDBC_E;
    if (q >= 0 && q < WOUT_E) {
        g_Woutb[q] = __float2bfloat16(wout[q]);
    }
}

// ---------------------------------------------------------------------------
// RMSNorm -> bf16 (norm_w folded into weights)
// ---------------------------------------------------------------------------
__global__ void rmsnorm_kernel(const float* __restrict__ x) {
    int t = blockIdx.x;
    int i = threadIdx.x;
    float v = x[(size_t)t * DMODEL + i];
    float ss = v * v;
    #pragma unroll
    for (int o = 16; o; o >>= 1) ss += __shfl_xor_sync(0xFFFFFFFFu, ss, o);
    __shared__ float red[8];
    if ((i & 31) == 0) red[i >> 5] = ss;
    __syncthreads();
    float tot = 0.f;
    #pragma unroll
    for (int j = 0; j < 8; j++) tot += red[j];
    float scale = rsqrtf(tot * (1.0f / DMODEL) + RMS_EPS);
    g_xnb[(size_t)t * DMODEL + i] = __float2bfloat16(v * scale);
}

// ---------------------------------------------------------------------------
// bf16 tensor-core GEMM: C[M,N] = A[M,K](bf16) * W[N,K](bf16)^T, fp32 accum.
// CTA tile 128x64x64, 128 threads (4 warps), warp tile 64x32, ldmatrix,
// mma m16n8k16. XOR-swizzled smem (chunk^(row&7)), 2-stage cp.async.
//  EPI 0: bf16 store (-> g_xzb)
//  EPI 1: n<512 softplus(v+bias)->g_deltab; 512..543 -> g_BC
//  EPI 2: fp32 v + resid -> Cf (out_proj)
// ---------------------------------------------------------------------------
#define GBM 128
#define GBN 64
#define GBK 64
#define AT_B (GBM * 128)                 // 16384
#define BT_B (GBN * 128)                 // 8192
#define STG_B (AT_B + BT_B)              // 24576
#define GSMEM (2 * STG_B)                // 49152

template<int EPI>
__global__ __launch_bounds__(128, 4)
void gemm_bf(const __nv_bfloat16* __restrict__ A,
             const __nv_bfloat16* __restrict__ W,
             float* __restrict__ Cf, __nv_bfloat16* __restrict__ Cb,
             int M, int N, int K,
             const float* __restrict__ bias,
             const float* __restrict__ resid) {
    extern __shared__ __align__(128) char dsm[];
    const uint32_t sbase = (uint32_t)__cvta_generic_to_shared(dsm);

    const int tid  = threadIdx.x;
    const int m0   = blockIdx.y * GBM;
    const int n0   = blockIdx.x * GBN;
    const int lane = tid & 31;
    const int wid  = tid >> 5;
    const int wm   = wid & 1;          // warp row (2)
    const int wn   = wid >> 1;         // warp col (2)
    const int g    = lane >> 2;        // 0..7
    const int t4   = lane & 3;         // 0..3

    float acc[4][4][4];
    #pragma unroll
    for (int mf = 0; mf < 4; mf++)
        #pragma unroll
        for (int nf = 0; nf < 4; nf++)
            #pragma unroll
            for (int r = 0; r < 4; r++) acc[mf][nf][r] = 0.0f;

    const uint32_t xr   = lane & 7;
    const uint32_t arow = (uint32_t)(wm * 64 + (lane & 15)) * 128;
    const uint32_t ca   = lane >> 4;
    const uint32_t brow = (uint32_t)(wn * 32 + (lane & 7) + ((lane & 16) ? 8 : 0)) * 128;
    const uint32_t cb_  = (lane >> 3) & 1;

    auto issue = [&](int it) {
        const int stage = it & 1;
        const uint32_t ab = sbase + stage * STG_B;
        const uint32_t bb = ab + AT_B;
        const int k0 = it * GBK;
        #pragma unroll
        for (int i = 0; i < 12; i++) {
            int idx = tid + i * 128;
            if (idx < 1024) {
                int r = idx >> 3, c = idx & 7;
                CP_ASYNC16(ab + (uint32_t)(r * 128 + ((c ^ (r & 7)) << 4)),
                           A + (size_t)(m0 + r) * K + k0 + c * 8);
            } else {
                int jdx = idx - 1024;
                int r = jdx >> 3, c = jdx & 7;
                CP_ASYNC16(bb + (uint32_t)(r * 128 + ((c ^ (r & 7)) << 4)),
                           W + (size_t)(n0 + r) * K + k0 + c * 8);
            }
        }
        CP_COMMIT();
    };

    const int niter = K / GBK;
    issue(0);

    for (int it = 0; it < niter; it++) {
        if (it) __syncthreads();
        if (it + 1 < niter) {
            issue(it + 1);
            asm volatile("cp.async.wait_group 1;");
        } else {
            asm volatile("cp.async.wait_group 0;");
        }
        __syncthreads();

        const uint32_t ab = sbase + (uint32_t)(it & 1) * STG_B;
        const uint32_t bb = ab + AT_B;

        #pragma unroll
        for (int kc = 0; kc < 4; kc++) {
            uint32_t af[4][4], bf[4][2];
            #pragma unroll
            for (int mf = 0; mf < 4; mf++) {
                LDSM_X4(af[mf][0], af[mf][1], af[mf][2], af[mf][3],
                        ab + arow + (uint32_t)(mf * 2048) +
                        ((((uint32_t)(kc * 2) + ca) ^ xr) << 4));
            }
            #pragma unroll
            for (int nfp = 0; nfp < 2; nfp++) {
                LDSM_X4(bf[2 * nfp][0], bf[2 * nfp][1],
                        bf[2 * nfp + 1][0], bf[2 * nfp + 1][1],
                        bb + brow + (uint32_t)(nfp * 2048) +
                        ((((uint32_t)(kc * 2) + cb_) ^ xr) << 4));
            }
            #pragma unroll
            for (int mf = 0; mf < 4; mf++)
                #pragma unroll
                for (int nf = 0; nf < 4; nf++)
                    mma_bf16(acc[mf][nf], af[mf], bf[nf]);
        }
    }

    // Epilogue
    #pragma unroll
    for (int mf = 0; mf < 4; mf++) {
        #pragma unroll
        for (int nf = 0; nf < 4; nf++) {
            #pragma unroll
            for (int r = 0; r < 4; r++) {
                int t = m0 + wm * 64 + mf * 16 + g + ((r >> 1) ? 8 : 0);
                int n = n0 + wn * 32 + nf * 8 + t4 * 2 + (r & 1);
                float v = acc[mf][nf][r];
                if (EPI == 0) {
                    Cb[(size_t)t * N + n] = __float2bfloat16(v);
                } else if (EPI == 1) {
                    if (n < 512) {
                        g_deltab[(size_t)t * DINNER + n] =
                            __float2bfloat16(softplus_f(v + bias[n]));
                    } else if (n < 544) {
                        g_BC[(size_t)t * 32 + (n - 512)] = v;
                    }
                } else { // EPI == 2
                    Cf[(size_t)t * N + n] = v + resid[(size_t)t * N + n];
                }
            }
        }
    }
}

// ---------------------------------------------------------------------------
// Causal depthwise conv (width 4) + bias + SiLU; bf16 in/out.
// Each thread: 2 adjacent channels x 8 timesteps (packed u32 loads/stores).
// ---------------------------------------------------------------------------
__global__ void conv_silu_kernel(const float* __restrict__ cw,
                                 const float* __restrict__ cb) {
    int q = blockIdx.x * blockDim.x + threadIdx.x;   // over (NTOK/8)*(DINNER/2)
    if (q >= (NTOK / 8) * (DINNER / 2)) return;
    int dp = (q & 255) * 2;                          // channel pair base
    int t0 = (q >> 8) * 8;
    int l0 = t0 & (SEQL - 1);
    float w0a = cw[dp * 4 + 0], w1a = cw[dp * 4 + 1];
    float w2a = cw[dp * 4 + 2], w3a = cw[dp * 4 + 3];
    float w0b = cw[dp * 4 + 4], w1b = cw[dp * 4 + 5];
    float w2b = cw[dp * 4 + 6], w3b = cw[dp * 4 + 7];
    float ba = cb[dp], bb = cb[dp + 1];
    float xa[11], xb[11];
    #pragma unroll
    for (int i = 0; i < 11; i++) {
        int li = l0 - 3 + i;
        if (li >= 0) {
            __nv_bfloat162 v = *(const __nv_bfloat162*)
                &g_xzb[(size_t)(t0 - 3 + i) * (2 * DINNER) + dp];
            xa[i] = __bfloat162float(v.x);
            xb[i] = __bfloat162float(v.y);
        } else { xa[i] = 0.0f; xb[i] = 0.0f; }
    }
    #pragma unroll
    for (int j = 0; j < 8; j++) {
        float va = fmaf(w3a, xa[j + 3], fmaf(w2a, xa[j + 2],
                   fmaf(w1a, xa[j + 1], fmaf(w0a, xa[j], ba))));
        float vb = fmaf(w3b, xb[j + 3], fmaf(w2b, xb[j + 2],
                   fmaf(w1b, xb[j + 1], fmaf(w0b, xb[j], bb))));
        __nv_bfloat162 o;
        o.x = __float2bfloat16(silu_f(va));
        o.y = __float2bfloat16(silu_f(vb));
        *(__nv_bfloat162*)&g_xcb[(size_t)(t0 + j) * DINNER + dp] = o;
    }
}

// ---------------------------------------------------------------------------
// Scan pass A: per-chunk end-state S and sum(delta).
// 256 threads/block; thread = (d, half), half owns 8 of the 16 n-states.
// ---------------------------------------------------------------------------
__global__ void scan_phaseA(const float* __restrict__ A_log) {
    int tid  = threadIdx.x;            // 0..255
    int half = tid & 1;                // n-group (0: n 0-7, 1: n 8-15)
    int d    = blockIdx.x * 128 + (tid >> 1);
    int c    = blockIdx.y;
    int b    = blockIdx.z;
    int nb   = half * 8;

    float A2[8], h[8];
    #pragma unroll
    for (int n = 0; n < 8; n++) {
        A2[n] = -__expf(A_log[d * NSTATE + nb + n]) * 1.4426950408889634f;
        h[n] = 0.0f;
    }
    float sdl = 0.0f;
    int tbase = b * SEQL + c * CT;
    #pragma unroll 2
    for (int s = 0; s < CT; s++) {
        int t = tbase + s;
        float dl = __bfloat162float(g_deltab[(size_t)t * DINNER + d]);
        float xv = __bfloat162float(g_xcb  [(size_t)t * DINNER + d]);
        float xd = xv * dl;
        sdl += dl;
        const float4* bc = (const float4*)(g_BC + (size_t)t * 32);
        float4 B0 = bc[half * 2], B1 = bc[half * 2 + 1];
        float bv[8] = {B0.x, B0.y, B0.z, B0.w, B1.x, B1.y, B1.z, B1.w};
        #pragma unroll
        for (int n = 0; n < 8; n++) {
            float dA = ex2f(dl * A2[n]);
            h[n] = fmaf(dA, h[n], xd * bv[n]);
        }
    }
    if (half == 0)
        g_sdl[((size_t)b * NCH + c) * DINNER + d] = sdl;
    size_t base = (((size_t)b * NCH + c) * NSTATE + nb) * DINNER + d;
    #pragma unroll
    for (int n = 0; n < 8; n++)
        g_S[base + (size_t)n * DINNER] = h[n];
}

// ---------------------------------------------------------------------------
// Scan pass B: sequential carry; P recomputed from sum(delta).
// ---------------------------------------------------------------------------
__global__ void scan_phaseB(const float* __restrict__ A_log) {
    int idx = blockIdx.x * blockDim.x + threadIdx.x;
    if (idx >= BATCH * NSTATE * DINNER) return;
    int d = idx & 511;
    int n = (idx >> 9) & 15;
    int b = idx >> 13;
    float A2 = -__expf(A_log[d * NSTATE + n]) * 1.4426950408889634f;
    float h = 0.0f;
    for (int c = 0; c < NCH; c++) {
        size_t o = (((size_t)b * NCH + c) * NSTATE + n) * DINNER + d;
        g_H[o] = h;
        float P = ex2f(A2 * g_sdl[((size_t)b * NCH + c) * DINNER + d]);
        h = fmaf(P, h, g_S[o]);
    }
}

// ---------------------------------------------------------------------------
// Scan pass C: rerun chunk with true initial state; +x*D, *silu(z); bf16 out.
// 256 threads/block; thread = (d, half); y combined via shfl within lane pair.
// ---------------------------------------------------------------------------
__global__ void scan_phaseC(const float* __restrict__ A_log,
                            const float* __restrict__ Dw) {
    int tid  = threadIdx.x;
    int half = tid & 1;
    int d    = blockIdx.x * 128 + (tid >> 1);
    int c    = blockIdx.y;
    int b    = blockIdx.z;
    int nb   = half * 8;

    float A2[8], h[8];
    size_t hbase = (((size_t)b * NCH + c) * NSTATE + nb) * DINNER + d;
    #pragma unroll
    for (int n = 0; n < 8; n++) {
        A2[n] = -__expf(A_log[d * NSTATE + nb + n]) * 1.4426950408889634f;
        h[n] = g_H[hbase + (size_t)n * DINNER];
    }
    float Dd = Dw[d];
    int tbase = b * SEQL + c * CT;
    #pragma unroll 2
    for (int s = 0; s < CT; s++) {
        int t = tbase + s;
        float dl = __bfloat162float(g_deltab[(size_t)t * DINNER + d]);
        float xv = __bfloat162float(g_xcb  [(size_t)t * DINNER + d]);
        float xd = xv * dl;
        const float4* bc = (const float4*)(g_BC + (size_t)t * 32);
        float4 B0 = bc[half * 2],     B1 = bc[half * 2 + 1];
        float4 C0 = bc[4 + half * 2], C1 = bc[4 + half * 2 + 1];
        float bv[8] = {B0.x, B0.y, B0.z, B0.w, B1.x, B1.y, B1.z, B1.w};
        float cv[8] = {C0.x, C0.y, C0.z, C0.w, C1.x, C1.y, C1.z, C1.w};
        float yv = 0.0f;
        #pragma unroll
        for (int n = 0; n < 8; n++) {
            float dA = ex2f(dl * A2[n]);
            h[n] = fmaf(dA, h[n], xd * bv[n]);
            yv = fmaf(h[n], cv[n], yv);
        }
        yv += __shfl_xor_sync(0xFFFFFFFFu, yv, 1);   // combine both n-halves
        if (half == 0) {
            float z = __bfloat162float(
                g_xzb[(size_t)t * (2 * DINNER) + DINNER + d]);
            g_yb[(size_t)t * DINNER + d] =
                __float2bfloat16((yv + xv * Dd) * silu_f(z));
        }
    }
}

// ---------------------------------------------------------------------------
// Launch
// ---------------------------------------------------------------------------
extern "C" void kernel_launch(void* const* d_in, const int* in_sizes, int n_in,
                              void* d_out, int out_size) {
    const float* x          = (const float*)d_in[0];
    const float* norm_w     = (const float*)d_in[1];
    const float* in_proj_w  = (const float*)d_in[2];
    const float* conv_w     = (const float*)d_in[3];
    const float* conv_b     = (const float*)d_in[4];
    const float* A_log      = (const float*)d_in[5];
    const float* projB_w    = (const float*)d_in[6];
    const float* projC_w    = (const float*)d_in[7];
    const float* projDelta_w= (const float*)d_in[8];
    const float* projDelta_b= (const float*)d_in[9];
    const float* Dw         = (const float*)d_in[10];
    const float* out_proj_w = (const float*)d_in[11];
    float* out = (float*)d_out;

    __nv_bfloat16 *p_xnb, *p_xzb, *p_xcb, *p_winb, *p_wdbcb, *p_woutb, *p_yb;
    cudaGetSymbolAddress((void**)&p_xnb,   g_xnb);
    cudaGetSymbolAddress((void**)&p_xzb,   g_xzb);
    cudaGetSymbolAddress((void**)&p_xcb,   g_xcb);
    cudaGetSymbolAddress((void**)&p_winb,  g_Winb);
    cudaGetSymbolAddress((void**)&p_wdbcb, g_Wdbcb);
    cudaGetSymbolAddress((void**)&p_woutb, g_Woutb);
    cudaGetSymbolAddress((void**)&p_yb,    g_yb);

    cudaFuncSetAttribute(gemm_bf<0>, cudaFuncAttributeMaxDynamicSharedMemorySize, GSMEM);
    cudaFuncSetAttribute(gemm_bf<1>, cudaFuncAttributeMaxDynamicSharedMemorySize, GSMEM);
    cudaFuncSetAttribute(gemm_bf<2>, cudaFuncAttributeMaxDynamicSharedMemorySize, GSMEM);

    // 1. weight prep
    prep_w_kernel<<<(WIN_E + WDBC_E + WOUT_E + 255) / 256, 256>>>(
        in_proj_w, norm_w, projDelta_w, projB_w, projC_w, out_proj_w);

    // 2. RMSNorm -> bf16
    rmsnorm_kernel<<<NTOK, DMODEL>>>(x);

    // 3. in_proj: [8192,256]x[1024,256]^T -> g_xzb (bf16)
    gemm_bf<0><<<dim3(2 * DINNER / GBN, NTOK / GBM), 128, GSMEM>>>(
        p_xnb, p_winb, nullptr, p_xzb, NTOK, 2 * DINNER, DMODEL, nullptr, nullptr);

    // 4. causal conv + silu
    conv_silu_kernel<<<((NTOK / 8) * (DINNER / 2) + 255) / 256, 256>>>(
        conv_w, conv_b);

    // 5. delta/B/C projections: [8192,512]x[576,512]^T
    gemm_bf<1><<<dim3(NDBC / GBN, NTOK / GBM), 128, GSMEM>>>(
        p_xcb, p_wdbcb, nullptr, nullptr, NTOK, NDBC, DINNER, projDelta_b, nullptr);

    // 6-8. chunked selective scan (n-split: 256 threads per 128 channels)
    scan_phaseA<<<dim3(DINNER / 128, NCH, BATCH), 256>>>(A_log);
    scan_phaseB<<<(BATCH * NSTATE * DINNER + 255) / 256, 256>>>(A_log);
    scan_phaseC<<<dim3(DINNER / 128, NCH, BATCH), 256>>>(A_log, Dw);

    // 9. out_proj + residual: [8192,512]x[256,512]^T + x
    gemm_bf<2><<<dim3(DMODEL / GBN, NTOK / GBM), 128, GSMEM>>>(
        p_yb, p_woutb, out, nullptr, NTOK, DMODEL, DINNER, nullptr, x);
}

// round 12
// speedup vs baseline: 1.2191x; 1.2191x over previous
#include <cuda_runtime.h>
#include <cuda_bf16.h>
#include <math.h>
#include <stdint.h>

// ---------------------------------------------------------------------------
// Problem constants
// ---------------------------------------------------------------------------
#define BATCH   4
#define SEQL    2048
#define DMODEL  256
#define DINNER  512
#define NSTATE  16
#define NTOK    (BATCH * SEQL)          // 8192
#define RMS_EPS 1.1920929e-07f

#define NCH     64                       // scan chunks
#define CT      (SEQL / NCH)             // 32 steps per chunk
#define NDBC    576                      // padded N for fused delta/B/C gemm (544 real)

// ---------------------------------------------------------------------------
// Scratch (static device globals; no allocation allowed)
// ---------------------------------------------------------------------------
__device__ __nv_bfloat16 g_xnb  [(size_t)NTOK * DMODEL];      // rmsnorm (bf16)
__device__ __nv_bfloat16 g_xzb  [(size_t)NTOK * 2 * DINNER];  // x_branch|z bf16
__device__ __nv_bfloat16 g_xcb  [(size_t)NTOK * DINNER];      // conv+silu bf16
__device__ __nv_bfloat16 g_deltab[(size_t)NTOK * DINNER];     // softplus(delta) bf16
__device__ float         g_BC   [(size_t)NTOK * 32];          // B(16) | C(16)
__device__ __nv_bfloat16 g_Winb [(size_t)(2 * DINNER) * DMODEL];
__device__ __nv_bfloat16 g_Wdbcb[(size_t)NDBC * DINNER];
__device__ __nv_bfloat16 g_Woutb[(size_t)DMODEL * DINNER];
__device__ __nv_bfloat16 g_yb   [(size_t)NTOK * DINNER];
__device__ float g_sdl[(size_t)BATCH * NCH * DINNER];          // per-chunk sum(delta)
__device__ float g_S  [(size_t)BATCH * NCH * NSTATE * DINNER];
__device__ float g_H  [(size_t)BATCH * NCH * NSTATE * DINNER];

// ---------------------------------------------------------------------------
// Helpers
// ---------------------------------------------------------------------------
__device__ __forceinline__ float ex2f(float x) {       // single MUFU.EX2
    float r;
    asm("ex2.approx.ftz.f32 %0, %1;" : "=f"(r) : "f"(x));
    return r;
}
__device__ __forceinline__ float silu_f(float v) { return v / (1.0f + __expf(-v)); }
__device__ __forceinline__ float softplus_f(float v) {
    return (v > 20.0f) ? v : __logf(1.0f + __expf(v));
}
__device__ __forceinline__ void mma_bf16(float (&d)[4], const uint32_t (&a)[4],
                                         const uint32_t (&b)[2]) {
    asm volatile(
        "mma.sync.aligned.m16n8k16.row.col.f32.bf16.bf16.f32 "
        "{%0,%1,%2,%3},{%4,%5,%6,%7},{%8,%9},{%0,%1,%2,%3};"
        : "+f"(d[0]), "+f"(d[1]), "+f"(d[2]), "+f"(d[3])
        : "r"(a[0]), "r"(a[1]), "r"(a[2]), "r"(a[3]), "r"(b[0]), "r"(b[1]));
}
#define LDSM_X4(r0, r1, r2, r3, addr)                                        \
    asm volatile("ldmatrix.sync.aligned.m8n8.x4.shared.b16 {%0,%1,%2,%3}, [%4];" \
                 : "=r"(r0), "=r"(r1), "=r"(r2), "=r"(r3) : "r"(addr))
#define CP_ASYNC16(dst, src) \
    asm volatile("cp.async.cg.shared.global [%0], [%1], 16;" :: "r"(dst), "l"(src))
#define CP_COMMIT() asm volatile("cp.async.commit_group;")

// ---------------------------------------------------------------------------
// Prep: weight bf16 conversions (norm_w folded into in_proj) + RMSNorm.
// Blocks [0, PREP_BLK) do elementwise weight conversion;
// blocks [PREP_BLK, PREP_BLK+NTOK) do one token's RMSNorm each (256 thr).
// ---------------------------------------------------------------------------
#define WIN_E  (2 * DINNER * DMODEL)    // 262144
#define WDBC_E (NDBC * DINNER)          // 294912
#define WOUT_E (DMODEL * DINNER)        // 131072
#define PREP_E (WIN_E + WDBC_E + WOUT_E)
#define PREP_BLK ((PREP_E + 255) / 256) // 2688
__global__ void prep_kernel(const float* __restrict__ win,
                            const float* __restrict__ normw,
                            const float* __restrict__ wd,
                            const float* __restrict__ wb,
                            const float* __restrict__ wc,
                            const float* __restrict__ wout,
                            const float* __restrict__ x) {
    if (blockIdx.x < PREP_BLK) {
        int idx = blockIdx.x * 256 + threadIdx.x;
        if (idx < WIN_E) {
            int k = idx & (DMODEL - 1);
            g_Winb[idx] = __float2bfloat16(win[idx] * normw[k]);
        }
        int j = idx - WIN_E;
        if (j >= 0 && j < WDBC_E) {
            int r = j / DINNER;
            int k = j - r * DINNER;
            float v;
            if      (r < 512) v = wd[(size_t)r * DINNER + k];
            else if (r < 528) v = wb[(size_t)(r - 512) * DINNER + k];
            else if (r < 544) v = wc[(size_t)(r - 528) * DINNER + k];
            else              v = 0.0f;
            g_Wdbcb[j] = __float2bfloat16(v);
        }
        int q = idx - WIN_E - WDBC_E;
        if (q >= 0 && q < WOUT_E) {
            g_Woutb[q] = __float2bfloat16(wout[q]);
        }
    } else {
        // RMSNorm: one token per block
        int t = blockIdx.x - PREP_BLK;
        int i = threadIdx.x;                 // 0..255
        float v = x[(size_t)t * DMODEL + i];
        float ss = v * v;
        #pragma unroll
        for (int o = 16; o; o >>= 1) ss += __shfl_xor_sync(0xFFFFFFFFu, ss, o);
        __shared__ float red[8];
        if ((i & 31) == 0) red[i >> 5] = ss;
        __syncthreads();
        float tot = 0.f;
        #pragma unroll
        for (int j = 0; j < 8; j++) tot += red[j];
        float scale = rsqrtf(tot * (1.0f / DMODEL) + RMS_EPS);
        g_xnb[(size_t)t * DMODEL + i] = __float2bfloat16(v * scale);
    }
}

// ---------------------------------------------------------------------------
// bf16 tensor-core GEMM: C[M,N] = A[M,K](bf16) * W[N,K](bf16)^T, fp32 accum.
// CTA tile 128x64x64, 128 threads (4 warps), warp tile 64x32, ldmatrix,
// mma m16n8k16. XOR-swizzled smem (chunk^(row&7)), 2-stage cp.async.
//  EPI 0: bf16 store (-> g_xzb)
//  EPI 1: n<512 softplus(v+bias)->g_deltab; 512..543 -> g_BC
//  EPI 2: fp32 v + resid -> Cf (out_proj)
// ---------------------------------------------------------------------------
#define GBM 128
#define GBN 64
#define GBK 64
#define AT_B (GBM * 128)                 // 16384
#define BT_B (GBN * 128)                 // 8192
#define STG_B (AT_B + BT_B)              // 24576
#define GSMEM (2 * STG_B)                // 49152

template<int EPI>
__global__ __launch_bounds__(128, 4)
void gemm_bf(const __nv_bfloat16* __restrict__ A,
             const __nv_bfloat16* __restrict__ W,
             float* __restrict__ Cf, __nv_bfloat16* __restrict__ Cb,
             int M, int N, int K,
             const float* __restrict__ bias,
             const float* __restrict__ resid) {
    extern __shared__ __align__(128) char dsm[];
    const uint32_t sbase = (uint32_t)__cvta_generic_to_shared(dsm);

    const int tid  = threadIdx.x;
    const int m0   = blockIdx.y * GBM;
    const int n0   = blockIdx.x * GBN;
    const int lane = tid & 31;
    const int wid  = tid >> 5;
    const int wm   = wid & 1;          // warp row (2)
    const int wn   = wid >> 1;         // warp col (2)
    const int g    = lane >> 2;        // 0..7
    const int t4   = lane & 3;         // 0..3

    float acc[4][4][4];
    #pragma unroll
    for (int mf = 0; mf < 4; mf++)
        #pragma unroll
        for (int nf = 0; nf < 4; nf++)
            #pragma unroll
            for (int r = 0; r < 4; r++) acc[mf][nf][r] = 0.0f;

    const uint32_t xr   = lane & 7;
    const uint32_t arow = (uint32_t)(wm * 64 + (lane & 15)) * 128;
    const uint32_t ca   = lane >> 4;
    const uint32_t brow = (uint32_t)(wn * 32 + (lane & 7) + ((lane & 16) ? 8 : 0)) * 128;
    const uint32_t cb_  = (lane >> 3) & 1;

    auto issue = [&](int it) {
        const int stage = it & 1;
        const uint32_t ab = sbase + stage * STG_B;
        const uint32_t bb = ab + AT_B;
        const int k0 = it * GBK;
        #pragma unroll
        for (int i = 0; i < 12; i++) {
            int idx = tid + i * 128;
            if (idx < 1024) {
                int r = idx >> 3, c = idx & 7;
                CP_ASYNC16(ab + (uint32_t)(r * 128 + ((c ^ (r & 7)) << 4)),
                           A + (size_t)(m0 + r) * K + k0 + c * 8);
            } else {
                int jdx = idx - 1024;
                int r = jdx >> 3, c = jdx & 7;
                CP_ASYNC16(bb + (uint32_t)(r * 128 + ((c ^ (r & 7)) << 4)),
                           W + (size_t)(n0 + r) * K + k0 + c * 8);
            }
        }
        CP_COMMIT();
    };

    const int niter = K / GBK;
    issue(0);

    for (int it = 0; it < niter; it++) {
        if (it) __syncthreads();
        if (it + 1 < niter) {
            issue(it + 1);
            asm volatile("cp.async.wait_group 1;");
        } else {
            asm volatile("cp.async.wait_group 0;");
        }
        __syncthreads();

        const uint32_t ab = sbase + (uint32_t)(it & 1) * STG_B;
        const uint32_t bb = ab + AT_B;

        #pragma unroll
        for (int kc = 0; kc < 4; kc++) {
            uint32_t af[4][4], bf[4][2];
            #pragma unroll
            for (int mf = 0; mf < 4; mf++) {
                LDSM_X4(af[mf][0], af[mf][1], af[mf][2], af[mf][3],
                        ab + arow + (uint32_t)(mf * 2048) +
                        ((((uint32_t)(kc * 2) + ca) ^ xr) << 4));
            }
            #pragma unroll
            for (int nfp = 0; nfp < 2; nfp++) {
                LDSM_X4(bf[2 * nfp][0], bf[2 * nfp][1],
                        bf[2 * nfp + 1][0], bf[2 * nfp + 1][1],
                        bb + brow + (uint32_t)(nfp * 2048) +
                        ((((uint32_t)(kc * 2) + cb_) ^ xr) << 4));
            }
            #pragma unroll
            for (int mf = 0; mf < 4; mf++)
                #pragma unroll
                for (int nf = 0; nf < 4; nf++)
                    mma_bf16(acc[mf][nf], af[mf], bf[nf]);
        }
    }

    // Epilogue
    #pragma unroll
    for (int mf = 0; mf < 4; mf++) {
        #pragma unroll
        for (int nf = 0; nf < 4; nf++) {
            #pragma unroll
            for (int r = 0; r < 4; r++) {
                int t = m0 + wm * 64 + mf * 16 + g + ((r >> 1) ? 8 : 0);
                int n = n0 + wn * 32 + nf * 8 + t4 * 2 + (r & 1);
                float v = acc[mf][nf][r];
                if (EPI == 0) {
                    Cb[(size_t)t * N + n] = __float2bfloat16(v);
                } else if (EPI == 1) {
                    if (n < 512) {
                        g_deltab[(size_t)t * DINNER + n] =
                            __float2bfloat16(softplus_f(v + bias[n]));
                    } else if (n < 544) {
                        g_BC[(size_t)t * 32 + (n - 512)] = v;
                    }
                } else { // EPI == 2
                    Cf[(size_t)t * N + n] = v + resid[(size_t)t * N + n];
                }
            }
        }
    }
}

// ---------------------------------------------------------------------------
// Causal depthwise conv (width 4) + bias + SiLU; bf16 in/out.
// Each thread: 2 adjacent channels x 8 timesteps (packed u32 loads/stores).
// ---------------------------------------------------------------------------
__global__ void conv_silu_kernel(const float* __restrict__ cw,
                                 const float* __restrict__ cb) {
    int q = blockIdx.x * blockDim.x + threadIdx.x;   // over (NTOK/8)*(DINNER/2)
    if (q >= (NTOK / 8) * (DINNER / 2)) return;
    int dp = (q & 255) * 2;                          // channel pair base
    int t0 = (q >> 8) * 8;
    int l0 = t0 & (SEQL - 1);
    float w0a = cw[dp * 4 + 0], w1a = cw[dp * 4 + 1];
    float w2a = cw[dp * 4 + 2], w3a = cw[dp * 4 + 3];
    float w0b = cw[dp * 4 + 4], w1b = cw[dp * 4 + 5];
    float w2b = cw[dp * 4 + 6], w3b = cw[dp * 4 + 7];
    float ba = cb[dp], bb = cb[dp + 1];
    float xa[11], xb[11];
    #pragma unroll
    for (int i = 0; i < 11; i++) {
        int li = l0 - 3 + i;
        if (li >= 0) {
            __nv_bfloat162 v = *(const __nv_bfloat162*)
                &g_xzb[(size_t)(t0 - 3 + i) * (2 * DINNER) + dp];
            xa[i] = __bfloat162float(v.x);
            xb[i] = __bfloat162float(v.y);
        } else { xa[i] = 0.0f; xb[i] = 0.0f; }
    }
    #pragma unroll
    for (int j = 0; j < 8; j++) {
        float va = fmaf(w3a, xa[j + 3], fmaf(w2a, xa[j + 2],
                   fmaf(w1a, xa[j + 1], fmaf(w0a, xa[j], ba))));
        float vb = fmaf(w3b, xb[j + 3], fmaf(w2b, xb[j + 2],
                   fmaf(w1b, xb[j + 1], fmaf(w0b, xb[j], bb))));
        __nv_bfloat162 o;
        o.x = __float2bfloat16(silu_f(va));
        o.y = __float2bfloat16(silu_f(vb));
        *(__nv_bfloat162*)&g_xcb[(size_t)(t0 + j) * DINNER + dp] = o;
    }
}

// ---------------------------------------------------------------------------
// Scan pass A: per-chunk end-state S and sum(delta). (R10 form)
// ---------------------------------------------------------------------------
__global__ void scan_phaseA(const float* __restrict__ A_log) {
    int d = blockIdx.x * 128 + threadIdx.x;
    int c = blockIdx.y;
    int b = blockIdx.z;

    float A2[NSTATE], h[NSTATE];
    #pragma unroll
    for (int n = 0; n < NSTATE; n++) {
        A2[n] = -__expf(A_log[d * NSTATE + n]) * 1.4426950408889634f;
        h[n] = 0.0f;
    }
    float sdl = 0.0f;
    int tbase = b * SEQL + c * CT;
    #pragma unroll 2
    for (int s = 0; s < CT; s++) {
        int t = tbase + s;
        float dl = __bfloat162float(g_deltab[(size_t)t * DINNER + d]);
        float xv = __bfloat162float(g_xcb  [(size_t)t * DINNER + d]);
        float xd = xv * dl;
        sdl += dl;
        const float4* bc = (const float4*)(g_BC + (size_t)t * 32);
        float4 b0 = bc[0], b1 = bc[1], b2 = bc[2], b3 = bc[3];
        float bvals[NSTATE] = {b0.x,b0.y,b0.z,b0.w, b1.x,b1.y,b1.z,b1.w,
                               b2.x,b2.y,b2.z,b2.w, b3.x,b3.y,b3.z,b3.w};
        #pragma unroll
        for (int n = 0; n < NSTATE; n++) {
            float dA = ex2f(dl * A2[n]);
            h[n] = fmaf(dA, h[n], xd * bvals[n]);
        }
    }
    g_sdl[((size_t)b * NCH + c) * DINNER + d] = sdl;
    size_t base = (((size_t)b * NCH + c) * NSTATE) * DINNER + d;
    #pragma unroll
    for (int n = 0; n < NSTATE; n++)
        g_S[base + (size_t)n * DINNER] = h[n];
}

// ---------------------------------------------------------------------------
// Scan pass B: sequential carry; P recomputed from sum(delta).
// ---------------------------------------------------------------------------
__global__ void scan_phaseB(const float* __restrict__ A_log) {
    int idx = blockIdx.x * blockDim.x + threadIdx.x;
    if (idx >= BATCH * NSTATE * DINNER) return;
    int d = idx & 511;
    int n = (idx >> 9) & 15;
    int b = idx >> 13;
    float A2 = -__expf(A_log[d * NSTATE + n]) * 1.4426950408889634f;
    float h = 0.0f;
    for (int c = 0; c < NCH; c++) {
        size_t o = (((size_t)b * NCH + c) * NSTATE + n) * DINNER + d;
        g_H[o] = h;
        float P = ex2f(A2 * g_sdl[((size_t)b * NCH + c) * DINNER + d]);
        h = fmaf(P, h, g_S[o]);
    }
}

// ---------------------------------------------------------------------------
// Scan pass C: rerun chunk with true initial state; +x*D, *silu(z). (R10 form)
// ---------------------------------------------------------------------------
__global__ void scan_phaseC(const float* __restrict__ A_log,
                            const float* __restrict__ Dw) {
    int d = blockIdx.x * 128 + threadIdx.x;
    int c = blockIdx.y;
    int b = blockIdx.z;

    float A2[NSTATE], h[NSTATE];
    size_t hbase = (((size_t)b * NCH + c) * NSTATE) * DINNER + d;
    #pragma unroll
    for (int n = 0; n < NSTATE; n++) {
        A2[n] = -__expf(A_log[d * NSTATE + n]) * 1.4426950408889634f;
        h[n] = g_H[hbase + (size_t)n * DINNER];
    }
    float Dd = Dw[d];
    int tbase = b * SEQL + c * CT;
    #pragma unroll 2
    for (int s = 0; s < CT; s++) {
        int t = tbase + s;
        float dl = __bfloat162float(g_deltab[(size_t)t * DINNER + d]);
        float xv = __bfloat162float(g_xcb  [(size_t)t * DINNER + d]);
        float xd = xv * dl;
        const float4* bc = (const float4*)(g_BC + (size_t)t * 32);
        float4 b0 = bc[0], b1 = bc[1], b2 = bc[2], b3 = bc[3];
        float4 c0 = bc[4], c1 = bc[5], c2 = bc[6], c3 = bc[7];
        float bvals[NSTATE] = {b0.x,b0.y,b0.z,b0.w, b1.x,b1.y,b1.z,b1.w,
                               b2.x,b2.y,b2.z,b2.w, b3.x,b3.y,b3.z,b3.w};
        float cvals[NSTATE] = {c0.x,c0.y,c0.z,c0.w, c1.x,c1.y,c1.z,c1.w,
                               c2.x,c2.y,c2.z,c2.w, c3.x,c3.y,c3.z,c3.w};
        float yv = 0.0f;
        #pragma unroll
        for (int n = 0; n < NSTATE; n++) {
            float dA = ex2f(dl * A2[n]);
            h[n] = fmaf(dA, h[n], xd * bvals[n]);
            yv = fmaf(h[n], cvals[n], yv);
        }
        float z = __bfloat162float(g_xzb[(size_t)t * (2 * DINNER) + DINNER + d]);
        g_yb[(size_t)t * DINNER + d] =
            __float2bfloat16((yv + xv * Dd) * silu_f(z));
    }
}

// ---------------------------------------------------------------------------
// Launch
// ---------------------------------------------------------------------------
extern "C" void kernel_launch(void* const* d_in, const int* in_sizes, int n_in,
                              void* d_out, int out_size) {
    const float* x          = (const float*)d_in[0];
    const float* norm_w     = (const float*)d_in[1];
    const float* in_proj_w  = (const float*)d_in[2];
    const float* conv_w     = (const float*)d_in[3];
    const float* conv_b     = (const float*)d_in[4];
    const float* A_log      = (const float*)d_in[5];
    const float* projB_w    = (const float*)d_in[6];
    const float* projC_w    = (const float*)d_in[7];
    const float* projDelta_w= (const float*)d_in[8];
    const float* projDelta_b= (const float*)d_in[9];
    const float* Dw         = (const float*)d_in[10];
    const float* out_proj_w = (const float*)d_in[11];
    float* out = (float*)d_out;

    __nv_bfloat16 *p_xnb, *p_xzb, *p_xcb, *p_winb, *p_wdbcb, *p_woutb, *p_yb;
    cudaGetSymbolAddress((void**)&p_xnb,   g_xnb);
    cudaGetSymbolAddress((void**)&p_xzb,   g_xzb);
    cudaGetSymbolAddress((void**)&p_xcb,   g_xcb);
    cudaGetSymbolAddress((void**)&p_winb,  g_Winb);
    cudaGetSymbolAddress((void**)&p_wdbcb, g_Wdbcb);
    cudaGetSymbolAddress((void**)&p_woutb, g_Woutb);
    cudaGetSymbolAddress((void**)&p_yb,    g_yb);

    cudaFuncSetAttribute(gemm_bf<0>, cudaFuncAttributeMaxDynamicSharedMemorySize, GSMEM);
    cudaFuncSetAttribute(gemm_bf<1>, cudaFuncAttributeMaxDynamicSharedMemorySize, GSMEM);
    cudaFuncSetAttribute(gemm_bf<2>, cudaFuncAttributeMaxDynamicSharedMemorySize, GSMEM);

    // 1. prep: weight conversions + RMSNorm (merged)
    prep_kernel<<<PREP_BLK + NTOK, 256>>>(
        in_proj_w, norm_w, projDelta_w, projB_w, projC_w, out_proj_w, x);

    // 2. in_proj: [8192,256]x[1024,256]^T -> g_xzb (bf16)
    gemm_bf<0><<<dim3(2 * DINNER / GBN, NTOK / GBM), 128, GSMEM>>>(
        p_xnb, p_winb, nullptr, p_xzb, NTOK, 2 * DINNER, DMODEL, nullptr, nullptr);

    // 3. causal conv + silu
    conv_silu_kernel<<<((NTOK / 8) * (DINNER / 2) + 255) / 256, 256>>>(
        conv_w, conv_b);

    // 4. delta/B/C projections: [8192,512]x[576,512]^T
    gemm_bf<1><<<dim3(NDBC / GBN, NTOK / GBM), 128, GSMEM>>>(
        p_xcb, p_wdbcb, nullptr, nullptr, NTOK, NDBC, DINNER, projDelta_b, nullptr);

    // 5-7. chunked selective scan
    scan_phaseA<<<dim3(DINNER / 128, NCH, BATCH), 128>>>(A_log);
    scan_phaseB<<<(BATCH * NSTATE * DINNER + 255) / 256, 256>>>(A_log);
    scan_phaseC<<<dim3(DINNER / 128, NCH, BATCH), 128>>>(A_log, Dw);

    // 8. out_proj + residual: [8192,512]x[256,512]^T + x
    gemm_bf<2><<<dim3(DMODEL / GBN, NTOK / GBM), 128, GSMEM>>>(
        p_yb, p_woutb, out, nullptr, NTOK, DMODEL, DINNER, nullptr, x);
}